// round 3
// baseline (speedup 1.0000x reference)
#include <cuda_runtime.h>

#define N_R 40000
#define N_U 30000
#define N_P 30000
#define NN  100000
#define EE  1600000
#define F   128
#define C   40
#define ZC  21            // stacked width: 5 + 7 + 6 + 3 bias-count cols
#define TN  128           // nodes per MLP block
#define HP  132           // padded h row stride (floats)
#define FP  132           // padded W2t row stride (floats)

// ---------------- device scratch (static, no allocation) ----------------
__device__ float g_h2[(size_t)NN * C];
__device__ float g_Ws[ZC * F];
__device__ int   g_deg[NN];
__device__ int   g_rowptr[NN + 1];
__device__ int   g_cursor[NN];
__device__ int   g_srcs[EE];
__device__ int   g_blocksum[128];
__device__ int   g_blockoff[128];

// ---------------- init: blocks 0..20 fuse weights, blocks 21.. zero g_deg ----------------
__global__ void k_init(const float* __restrict__ Wr, const float* __restrict__ br,
                       const float* __restrict__ Wu, const float* __restrict__ bu,
                       const float* __restrict__ Wp, const float* __restrict__ bp,
                       const float* __restrict__ W1)
{
    if (blockIdx.x < ZC) {
        int row = blockIdx.x;
        int f   = threadIdx.x;     // 0..127
        const float* v;
        if (row < 5)        v = Wr + row * F;
        else if (row < 12)  v = Wu + (row - 5) * F;
        else if (row < 18)  v = Wp + (row - 12) * F;
        else if (row == 18) v = br;
        else if (row == 19) v = bu;
        else                v = bp;
        float acc = 0.f;
        for (int j = 0; j < F; j++) acc += v[j] * W1[j * F + f];
        g_Ws[row * F + f] = acc;
    } else {
        int i = (blockIdx.x - ZC) * blockDim.x + threadIdx.x;
        if (i < NN) g_deg[i] = 0;
    }
}

// ---------------- histogram: 4 edges per thread ----------------
__global__ void k_hist(const int* __restrict__ dst)
{
    int t = blockIdx.x * blockDim.x + threadIdx.x;
    if (t < EE / 4) {
        int4 d = ((const int4*)dst)[t];
        atomicAdd(&g_deg[d.x], 1);
        atomicAdd(&g_deg[d.y], 1);
        atomicAdd(&g_deg[d.z], 1);
        atomicAdd(&g_deg[d.w], 1);
    }
}

// ---------------- parallel scan (3 stages) ----------------
__global__ void k_scan1()
{
    __shared__ int wsum[8];
    int t = threadIdx.x;               // 0..255
    int lane = t & 31, wid = t >> 5;
    int i0 = blockIdx.x * 1024 + t * 4;
    int v[4], tsum = 0;
    #pragma unroll
    for (int k = 0; k < 4; k++) {
        v[k] = (i0 + k < NN) ? g_deg[i0 + k] : 0;
        tsum += v[k];
    }
    int incl = tsum;
    #pragma unroll
    for (int off = 1; off < 32; off <<= 1) {
        int x = __shfl_up_sync(0xffffffffu, incl, off);
        if (lane >= off) incl += x;
    }
    if (lane == 31) wsum[wid] = incl;
    __syncthreads();
    if (t < 8) {
        int w = wsum[t], wi = w;
        #pragma unroll
        for (int off = 1; off < 8; off <<= 1) {
            int x = __shfl_up_sync(0xffu, wi, off);
            if (t >= off) wi += x;
        }
        wsum[t] = wi - w;
        if (t == 7) g_blocksum[blockIdx.x] = wi;
    }
    __syncthreads();
    int excl = wsum[wid] + (incl - tsum);
    int run = 0;
    #pragma unroll
    for (int k = 0; k < 4; k++) {
        if (i0 + k < NN) g_rowptr[i0 + k] = excl + run;
        run += v[k];
    }
}

__global__ void k_scan2(int nblocks)
{
    __shared__ int ws[4];
    int t = threadIdx.x;               // 0..127
    int lane = t & 31, wid = t >> 5;
    int v = (t < nblocks) ? g_blocksum[t] : 0;
    int incl = v;
    #pragma unroll
    for (int off = 1; off < 32; off <<= 1) {
        int x = __shfl_up_sync(0xffffffffu, incl, off);
        if (lane >= off) incl += x;
    }
    if (lane == 31) ws[wid] = incl;
    __syncthreads();
    if (t == 0) {
        int a = 0;
        #pragma unroll
        for (int i = 0; i < 4; i++) { int x = ws[i]; ws[i] = a; a += x; }
    }
    __syncthreads();
    if (t < nblocks) g_blockoff[t] = ws[wid] + incl - v;
}

__global__ void k_scan3()
{
    int i = blockIdx.x * blockDim.x + threadIdx.x;
    if (i < NN) {
        int r = g_rowptr[i] + g_blockoff[i >> 10];
        g_rowptr[i] = r;
        g_cursor[i] = r;
    }
    if (i == 0) g_rowptr[NN] = EE;
}

// ---------------- scatter: 4 edges per thread ----------------
__global__ void k_scatter(const int* __restrict__ src, const int* __restrict__ dst)
{
    int t = blockIdx.x * blockDim.x + threadIdx.x;
    if (t < EE / 4) {
        int4 d = ((const int4*)dst)[t];
        int4 s = ((const int4*)src)[t];
        g_srcs[atomicAdd(&g_cursor[d.x], 1)] = s.x;
        g_srcs[atomicAdd(&g_cursor[d.y], 1)] = s.y;
        g_srcs[atomicAdd(&g_cursor[d.z], 1)] = s.z;
        g_srcs[atomicAdd(&g_cursor[d.w], 1)] = s.w;
    }
}

// ---------------- fused aggz + 2-layer MLP: 128 nodes per block, 256 threads ----------------
__global__ void __launch_bounds__(256, 1)
k_mlp(const float* __restrict__ xr, const float* __restrict__ xu,
      const float* __restrict__ xp, const float* __restrict__ W2)
{
    extern __shared__ float sm[];
    float* Wss = sm;                  // ZC*F   = 2688
    float* W2t = Wss + ZC * F;        // C*FP   = 5280  (transposed, padded)
    float* zsm = W2t + C * FP;        // TN*ZC  = 2688
    float* hsm = zsm + TN * ZC;       // TN*HP  = 16896

    int tid = threadIdx.x;            // 0..255
    int nodeBase = blockIdx.x * TN;

    for (int i = tid; i < ZC * F; i += 256) Wss[i] = g_Ws[i];
    for (int i = tid; i < C * F; i += 256) {
        int col = i >> 7, k = i & (F - 1);
        W2t[col * FP + k] = W2[k * C + col];
    }

    // ---- phase 0: aggregate raw features into zsm (8 lanes per node, 4 passes)
    {
        int lane = tid & 7;
        #pragma unroll
        for (int pass = 0; pass < 4; pass++) {
            int nl = (tid >> 3) + pass * 32;
            int node = nodeBase + nl;
            float aR = 0.f, aU = 0.f, aP = 0.f;
            int   cR = 0,   cU = 0,   cP = 0;
            if (node < NN) {
                int b = g_rowptr[node], e = g_rowptr[node + 1];
                int j = b;
                for (; j + 1 < e; j += 2) {
                    int s0 = g_srcs[j];
                    int s1 = g_srcs[j + 1];
                    if (s0 < N_R)            { if (lane < 5) aR += xr[s0 * 5 + lane]; cR++; }
                    else if (s0 < N_R + N_U) { if (lane < 7) aU += xu[(s0 - N_R) * 7 + lane]; cU++; }
                    else                     { if (lane < 6) aP += xp[(s0 - N_R - N_U) * 6 + lane]; cP++; }
                    if (s1 < N_R)            { if (lane < 5) aR += xr[s1 * 5 + lane]; cR++; }
                    else if (s1 < N_R + N_U) { if (lane < 7) aU += xu[(s1 - N_R) * 7 + lane]; cU++; }
                    else                     { if (lane < 6) aP += xp[(s1 - N_R - N_U) * 6 + lane]; cP++; }
                }
                if (j < e) {
                    int s0 = g_srcs[j];
                    if (s0 < N_R)            { if (lane < 5) aR += xr[s0 * 5 + lane]; cR++; }
                    else if (s0 < N_R + N_U) { if (lane < 7) aU += xu[(s0 - N_R) * 7 + lane]; cU++; }
                    else                     { if (lane < 6) aP += xp[(s0 - N_R - N_U) * 6 + lane]; cP++; }
                }
            }
            float* zr = zsm + nl * ZC;
            if (lane < 5) zr[lane]      = aR;
            if (lane < 7) zr[5 + lane]  = aU;
            if (lane < 6) zr[12 + lane] = aP;
            if (lane == 7) {
                zr[18] = (float)cR;
                zr[19] = (float)cU;
                zr[20] = (float)cP;
            }
        }
    }
    __syncthreads();

    // ---- phase A: h = relu(z @ Ws); thread = 8 nodes x 8 cols
    {
        int ng = tid >> 4;            // 0..15 -> nodes ng*8..+7
        int cl = tid & 15;            // cols cl + 16*i
        int n0 = ng * 8;
        float acc[8][8];
        #pragma unroll
        for (int j = 0; j < 8; j++)
            #pragma unroll
            for (int i = 0; i < 8; i++) acc[j][i] = 0.f;
        #pragma unroll
        for (int k = 0; k < ZC; k++) {
            float w[8];
            #pragma unroll
            for (int i = 0; i < 8; i++) w[i] = Wss[k * F + cl + 16 * i];
            #pragma unroll
            for (int j = 0; j < 8; j++) {
                float z = zsm[(n0 + j) * ZC + k];
                #pragma unroll
                for (int i = 0; i < 8; i++) acc[j][i] += z * w[i];
            }
        }
        #pragma unroll
        for (int j = 0; j < 8; j++)
            #pragma unroll
            for (int i = 0; i < 8; i++)
                hsm[(n0 + j) * HP + cl + 16 * i] = fmaxf(acc[j][i], 0.f);
    }
    __syncthreads();

    // ---- phase B: h2 = h @ W2; thread = 4 nodes x 5 cols, float4 along hidden dim
    {
        int ng = tid >> 3;            // 0..31 -> nodes ng*4..+3
        int cl = tid & 7;             // cols cl + 8*i, i<5
        int n0 = ng * 4;
        float a[4][5];
        #pragma unroll
        for (int j = 0; j < 4; j++)
            #pragma unroll
            for (int i = 0; i < 5; i++) a[j][i] = 0.f;
        #pragma unroll 4
        for (int c = 0; c < F; c += 4) {
            float4 h[4];
            #pragma unroll
            for (int j = 0; j < 4; j++)
                h[j] = *(const float4*)&hsm[(n0 + j) * HP + c];
            float4 w[5];
            #pragma unroll
            for (int i = 0; i < 5; i++)
                w[i] = *(const float4*)&W2t[(cl + 8 * i) * FP + c];
            #pragma unroll
            for (int j = 0; j < 4; j++)
                #pragma unroll
                for (int i = 0; i < 5; i++) {
                    a[j][i] += h[j].x * w[i].x;
                    a[j][i] += h[j].y * w[i].y;
                    a[j][i] += h[j].z * w[i].z;
                    a[j][i] += h[j].w * w[i].w;
                }
        }
        #pragma unroll
        for (int j = 0; j < 4; j++) {
            int node = nodeBase + n0 + j;
            if (node < NN) {
                #pragma unroll
                for (int i = 0; i < 5; i++)
                    g_h2[(size_t)node * C + cl + 8 * i] = a[j][i];
            }
        }
    }
}

// ---------------- layer-2 aggregate: warp per node, 4-edge unroll ----------------
__global__ void k_agg2(float* __restrict__ out)
{
    int gw = (blockIdx.x * blockDim.x + threadIdx.x) >> 5;
    if (gw >= NN) return;
    int lane = threadIdx.x & 31;
    int b = g_rowptr[gw], e = g_rowptr[gw + 1];
    float a0 = 0.f, a1 = 0.f;
    int j = b;
    for (; j + 3 < e; j += 4) {
        int s0 = g_srcs[j], s1 = g_srcs[j + 1], s2 = g_srcs[j + 2], s3 = g_srcs[j + 3];
        const float* r0 = g_h2 + (size_t)s0 * C;
        const float* r1 = g_h2 + (size_t)s1 * C;
        const float* r2 = g_h2 + (size_t)s2 * C;
        const float* r3 = g_h2 + (size_t)s3 * C;
        float v0 = r0[lane], v1 = r1[lane], v2 = r2[lane], v3 = r3[lane];
        a0 += (v0 + v1) + (v2 + v3);
        if (lane < C - 32) {
            float u0 = r0[32 + lane], u1 = r1[32 + lane], u2 = r2[32 + lane], u3 = r3[32 + lane];
            a1 += (u0 + u1) + (u2 + u3);
        }
    }
    for (; j < e; j++) {
        int s0 = g_srcs[j];
        const float* r0 = g_h2 + (size_t)s0 * C;
        a0 += r0[lane];
        if (lane < C - 32) a1 += r0[32 + lane];
    }
    out[(size_t)gw * C + lane] = a0;
    if (lane < C - 32) out[(size_t)gw * C + 32 + lane] = a1;
}

// ---------------- launch ----------------
extern "C" void kernel_launch(void* const* d_in, const int* in_sizes, int n_in,
                              void* d_out, int out_size)
{
    const float* xr = (const float*)d_in[0];
    const float* xu = (const float*)d_in[1];
    const float* xp = (const float*)d_in[2];
    const int*   ei = (const int*)  d_in[3];
    const float* Wr = (const float*)d_in[4];
    const float* br = (const float*)d_in[5];
    const float* Wu = (const float*)d_in[6];
    const float* bu = (const float*)d_in[7];
    const float* Wp = (const float*)d_in[8];
    const float* bp = (const float*)d_in[9];
    const float* W1 = (const float*)d_in[10];
    const float* W2 = (const float*)d_in[11];
    float* out = (float*)d_out;

    const int* src = ei;
    const int* dst = ei + EE;

    const int smem_mlp = (ZC * F + C * FP + TN * ZC + TN * HP) * sizeof(float);
    cudaFuncSetAttribute(k_mlp, cudaFuncAttributeMaxDynamicSharedMemorySize, smem_mlp);

    const int nScanBlocks = (NN + 1023) / 1024;   // 98
    const int nZeroBlocks = (NN + 127) / 128;

    k_init<<<ZC + nZeroBlocks, 128>>>(Wr, br, Wu, bu, Wp, bp, W1);
    k_hist<<<(EE / 4 + 255) / 256, 256>>>(dst);
    k_scan1<<<nScanBlocks, 256>>>();
    k_scan2<<<1, 128>>>(nScanBlocks);
    k_scan3<<<(NN + 255) / 256, 256>>>();
    k_scatter<<<(EE / 4 + 255) / 256, 256>>>(src, dst);
    k_mlp<<<(NN + TN - 1) / TN, 256, smem_mlp>>>(xr, xu, xp, W2);
    k_agg2<<<(NN * 32 + 255) / 256, 256>>>(out);
}

// round 4
// speedup vs baseline: 1.5159x; 1.5159x over previous
#include <cuda_runtime.h>

#define N_R 40000
#define N_U 30000
#define N_P 30000
#define NN  100000
#define EE  1600000
#define F   128
#define C   40
#define ZC  21            // stacked width: 5 + 7 + 6 + 3 bias-count cols
#define TN  128           // nodes per MLP block
#define HP  132           // padded h row stride (floats)
#define FP  132           // padded W2t row stride (floats)

// ---------------- device scratch (static, no allocation) ----------------
__device__ float g_z [(size_t)(NN + 64) * ZC];
__device__ float g_h2[(size_t)NN * C];
__device__ float g_Ws[ZC * F];
__device__ int   g_deg[NN];
__device__ int   g_rowptr[NN + 1];
__device__ int   g_cursor[NN];
__device__ int   g_srcs[EE];
__device__ int   g_blocksum[128];
__device__ int   g_blockoff[128];

// ---------------- init: blocks 0..20 fuse weights, blocks 21.. zero g_deg ----------------
__global__ void k_init(const float* __restrict__ Wr, const float* __restrict__ br,
                       const float* __restrict__ Wu, const float* __restrict__ bu,
                       const float* __restrict__ Wp, const float* __restrict__ bp,
                       const float* __restrict__ W1)
{
    if (blockIdx.x < ZC) {
        int row = blockIdx.x;
        int f   = threadIdx.x;     // 0..127
        const float* v;
        if (row < 5)        v = Wr + row * F;
        else if (row < 12)  v = Wu + (row - 5) * F;
        else if (row < 18)  v = Wp + (row - 12) * F;
        else if (row == 18) v = br;
        else if (row == 19) v = bu;
        else                v = bp;
        float acc = 0.f;
        for (int j = 0; j < F; j++) acc += v[j] * W1[j * F + f];
        g_Ws[row * F + f] = acc;
    } else {
        int i = (blockIdx.x - ZC) * blockDim.x + threadIdx.x;
        if (i < NN) g_deg[i] = 0;
    }
}

// ---------------- histogram ----------------
__global__ void k_hist(const int* __restrict__ dst)
{
    int e = blockIdx.x * blockDim.x + threadIdx.x;
    if (e < EE) atomicAdd(&g_deg[dst[e]], 1);
}

// ---------------- parallel scan (3 stages) ----------------
__global__ void k_scan1()
{
    __shared__ int wsum[8];
    int t = threadIdx.x;               // 0..255
    int lane = t & 31, wid = t >> 5;
    int i0 = blockIdx.x * 1024 + t * 4;
    int v[4], tsum = 0;
    #pragma unroll
    for (int k = 0; k < 4; k++) {
        v[k] = (i0 + k < NN) ? g_deg[i0 + k] : 0;
        tsum += v[k];
    }
    int incl = tsum;
    #pragma unroll
    for (int off = 1; off < 32; off <<= 1) {
        int x = __shfl_up_sync(0xffffffffu, incl, off);
        if (lane >= off) incl += x;
    }
    if (lane == 31) wsum[wid] = incl;
    __syncthreads();
    if (t < 8) {
        int w = wsum[t], wi = w;
        #pragma unroll
        for (int off = 1; off < 8; off <<= 1) {
            int x = __shfl_up_sync(0xffu, wi, off);
            if (t >= off) wi += x;
        }
        wsum[t] = wi - w;
        if (t == 7) g_blocksum[blockIdx.x] = wi;
    }
    __syncthreads();
    int excl = wsum[wid] + (incl - tsum);
    int run = 0;
    #pragma unroll
    for (int k = 0; k < 4; k++) {
        if (i0 + k < NN) g_rowptr[i0 + k] = excl + run;
        run += v[k];
    }
}

__global__ void k_scan2(int nblocks)
{
    __shared__ int ws[4];
    int t = threadIdx.x;               // 0..127
    int lane = t & 31, wid = t >> 5;
    int v = (t < nblocks) ? g_blocksum[t] : 0;
    int incl = v;
    #pragma unroll
    for (int off = 1; off < 32; off <<= 1) {
        int x = __shfl_up_sync(0xffffffffu, incl, off);
        if (lane >= off) incl += x;
    }
    if (lane == 31) ws[wid] = incl;
    __syncthreads();
    if (t == 0) {
        int a = 0;
        #pragma unroll
        for (int i = 0; i < 4; i++) { int x = ws[i]; ws[i] = a; a += x; }
    }
    __syncthreads();
    if (t < nblocks) g_blockoff[t] = ws[wid] + incl - v;
}

__global__ void k_scan3()
{
    int i = blockIdx.x * blockDim.x + threadIdx.x;
    if (i < NN) {
        int r = g_rowptr[i] + g_blockoff[i >> 10];
        g_rowptr[i] = r;
        g_cursor[i] = r;
    }
    if (i == 0) g_rowptr[NN] = EE;
}

// ---------------- scatter ----------------
__global__ void k_scatter(const int* __restrict__ src, const int* __restrict__ dst)
{
    int e = blockIdx.x * blockDim.x + threadIdx.x;
    if (e < EE) {
        int d = dst[e];
        int p = atomicAdd(&g_cursor[d], 1);
        g_srcs[p] = src[e];
    }
}

// ---------------- layer-1 raw aggregate: z[dst] = sum of src raw feats (by segment)
// 8 lanes per node (high occupancy, standalone)
__global__ void k_aggz(const float* __restrict__ xr, const float* __restrict__ xu,
                       const float* __restrict__ xp)
{
    int gid  = blockIdx.x * blockDim.x + threadIdx.x;
    int node = gid >> 3;
    if (node >= NN) return;
    int lane = gid & 7;
    int b = g_rowptr[node], e = g_rowptr[node + 1];
    float aR = 0.f, aU = 0.f, aP = 0.f;
    int   cR = 0,   cU = 0,   cP = 0;
    int j = b;
    for (; j + 1 < e; j += 2) {
        int s0 = g_srcs[j];
        int s1 = g_srcs[j + 1];
        if (s0 < N_R)            { if (lane < 5) aR += xr[s0 * 5 + lane]; cR++; }
        else if (s0 < N_R + N_U) { if (lane < 7) aU += xu[(s0 - N_R) * 7 + lane]; cU++; }
        else                     { if (lane < 6) aP += xp[(s0 - N_R - N_U) * 6 + lane]; cP++; }
        if (s1 < N_R)            { if (lane < 5) aR += xr[s1 * 5 + lane]; cR++; }
        else if (s1 < N_R + N_U) { if (lane < 7) aU += xu[(s1 - N_R) * 7 + lane]; cU++; }
        else                     { if (lane < 6) aP += xp[(s1 - N_R - N_U) * 6 + lane]; cP++; }
    }
    if (j < e) {
        int s0 = g_srcs[j];
        if (s0 < N_R)            { if (lane < 5) aR += xr[s0 * 5 + lane]; cR++; }
        else if (s0 < N_R + N_U) { if (lane < 7) aU += xu[(s0 - N_R) * 7 + lane]; cU++; }
        else                     { if (lane < 6) aP += xp[(s0 - N_R - N_U) * 6 + lane]; cP++; }
    }
    float* zr = g_z + (size_t)node * ZC;
    if (lane < 5) zr[lane]      = aR;
    if (lane < 7) zr[5 + lane]  = aU;
    if (lane < 6) zr[12 + lane] = aP;
    if (lane == 7) {
        zr[18] = (float)cR;
        zr[19] = (float)cU;
        zr[20] = (float)cP;
    }
}

// ---------------- 2-layer MLP: h2 = relu(z@Ws)@W2, 128 nodes / 256 threads ----------------
__global__ void k_mlp(const float* __restrict__ W2)
{
    extern __shared__ float sm[];
    float* Wss = sm;                  // ZC*F   = 2688
    float* W2t = Wss + ZC * F;        // C*FP   = 5280  (transposed, padded)
    float* zsm = W2t + C * FP;        // TN*ZC  = 2688
    float* hsm = zsm + TN * ZC;       // TN*HP  = 16896

    int tid = threadIdx.x;            // 0..255
    int nodeBase = blockIdx.x * TN;

    for (int i = tid; i < ZC * F; i += 256) Wss[i] = g_Ws[i];
    for (int i = tid; i < C * F; i += 256) {
        int col = i >> 7, k = i & (F - 1);
        W2t[col * FP + k] = W2[k * C + col];
    }
    // z rows contiguous (g_z is padded past NN, safe to over-read)
    const float* zg = g_z + (size_t)nodeBase * ZC;
    for (int i = tid; i < TN * ZC; i += 256) zsm[i] = zg[i];
    __syncthreads();

    // ---- phase A: h = relu(z @ Ws); thread = 8 nodes x 8 cols
    {
        int ng = tid >> 4;            // 0..15 -> nodes ng*8..+7
        int cl = tid & 15;            // cols cl + 16*i
        int n0 = ng * 8;
        float acc[8][8];
        #pragma unroll
        for (int j = 0; j < 8; j++)
            #pragma unroll
            for (int i = 0; i < 8; i++) acc[j][i] = 0.f;
        #pragma unroll
        for (int k = 0; k < ZC; k++) {
            float w[8];
            #pragma unroll
            for (int i = 0; i < 8; i++) w[i] = Wss[k * F + cl + 16 * i];
            #pragma unroll
            for (int j = 0; j < 8; j++) {
                float z = zsm[(n0 + j) * ZC + k];
                #pragma unroll
                for (int i = 0; i < 8; i++) acc[j][i] += z * w[i];
            }
        }
        #pragma unroll
        for (int j = 0; j < 8; j++)
            #pragma unroll
            for (int i = 0; i < 8; i++)
                hsm[(n0 + j) * HP + cl + 16 * i] = fmaxf(acc[j][i], 0.f);
    }
    __syncthreads();

    // ---- phase B: h2 = h @ W2; thread = 4 nodes x 5 cols, float4 along hidden dim
    {
        int ng = tid >> 3;            // 0..31 -> nodes ng*4..+3
        int cl = tid & 7;             // cols cl + 8*i, i<5
        int n0 = ng * 4;
        float a[4][5];
        #pragma unroll
        for (int j = 0; j < 4; j++)
            #pragma unroll
            for (int i = 0; i < 5; i++) a[j][i] = 0.f;
        #pragma unroll 4
        for (int c = 0; c < F; c += 4) {
            float4 h[4];
            #pragma unroll
            for (int j = 0; j < 4; j++)
                h[j] = *(const float4*)&hsm[(n0 + j) * HP + c];
            float4 w[5];
            #pragma unroll
            for (int i = 0; i < 5; i++)
                w[i] = *(const float4*)&W2t[(cl + 8 * i) * FP + c];
            #pragma unroll
            for (int j = 0; j < 4; j++)
                #pragma unroll
                for (int i = 0; i < 5; i++) {
                    a[j][i] += h[j].x * w[i].x;
                    a[j][i] += h[j].y * w[i].y;
                    a[j][i] += h[j].z * w[i].z;
                    a[j][i] += h[j].w * w[i].w;
                }
        }
        #pragma unroll
        for (int j = 0; j < 4; j++) {
            int node = nodeBase + n0 + j;
            if (node < NN) {
                #pragma unroll
                for (int i = 0; i < 5; i++)
                    g_h2[(size_t)node * C + cl + 8 * i] = a[j][i];
            }
        }
    }
}

// ---------------- layer-2 aggregate: warp per node, 4-edge unroll ----------------
__global__ void k_agg2(float* __restrict__ out)
{
    int gw = (blockIdx.x * blockDim.x + threadIdx.x) >> 5;
    if (gw >= NN) return;
    int lane = threadIdx.x & 31;
    int b = g_rowptr[gw], e = g_rowptr[gw + 1];
    float a0 = 0.f, a1 = 0.f;
    int j = b;
    for (; j + 3 < e; j += 4) {
        int s0 = g_srcs[j], s1 = g_srcs[j + 1], s2 = g_srcs[j + 2], s3 = g_srcs[j + 3];
        const float* r0 = g_h2 + (size_t)s0 * C;
        const float* r1 = g_h2 + (size_t)s1 * C;
        const float* r2 = g_h2 + (size_t)s2 * C;
        const float* r3 = g_h2 + (size_t)s3 * C;
        float v0 = r0[lane], v1 = r1[lane], v2 = r2[lane], v3 = r3[lane];
        a0 += (v0 + v1) + (v2 + v3);
        if (lane < C - 32) {
            float u0 = r0[32 + lane], u1 = r1[32 + lane], u2 = r2[32 + lane], u3 = r3[32 + lane];
            a1 += (u0 + u1) + (u2 + u3);
        }
    }
    for (; j < e; j++) {
        int s0 = g_srcs[j];
        const float* r0 = g_h2 + (size_t)s0 * C;
        a0 += r0[lane];
        if (lane < C - 32) a1 += r0[32 + lane];
    }
    out[(size_t)gw * C + lane] = a0;
    if (lane < C - 32) out[(size_t)gw * C + 32 + lane] = a1;
}

// ---------------- launch ----------------
extern "C" void kernel_launch(void* const* d_in, const int* in_sizes, int n_in,
                              void* d_out, int out_size)
{
    const float* xr = (const float*)d_in[0];
    const float* xu = (const float*)d_in[1];
    const float* xp = (const float*)d_in[2];
    const int*   ei = (const int*)  d_in[3];
    const float* Wr = (const float*)d_in[4];
    const float* br = (const float*)d_in[5];
    const float* Wu = (const float*)d_in[6];
    const float* bu = (const float*)d_in[7];
    const float* Wp = (const float*)d_in[8];
    const float* bp = (const float*)d_in[9];
    const float* W1 = (const float*)d_in[10];
    const float* W2 = (const float*)d_in[11];
    float* out = (float*)d_out;

    const int* src = ei;
    const int* dst = ei + EE;

    const int smem_mlp = (ZC * F + C * FP + TN * ZC + TN * HP) * sizeof(float);
    cudaFuncSetAttribute(k_mlp, cudaFuncAttributeMaxDynamicSharedMemorySize, smem_mlp);

    const int nScanBlocks = (NN + 1023) / 1024;   // 98
    const int nZeroBlocks = (NN + 127) / 128;

    k_init<<<ZC + nZeroBlocks, 128>>>(Wr, br, Wu, bu, Wp, bp, W1);
    k_hist<<<(EE + 255) / 256, 256>>>(dst);
    k_scan1<<<nScanBlocks, 256>>>();
    k_scan2<<<1, 128>>>(nScanBlocks);
    k_scan3<<<(NN + 255) / 256, 256>>>();
    k_scatter<<<(EE + 255) / 256, 256>>>(src, dst);
    k_aggz<<<(NN * 8 + 255) / 256, 256>>>(xr, xu, xp);
    k_mlp<<<(NN + TN - 1) / TN, 256, smem_mlp>>>(W2);
    k_agg2<<<(NN * 32 + 255) / 256, 256>>>(out);
}